// round 1
// baseline (speedup 1.0000x reference)
#include <cuda_runtime.h>
#include <math.h>

#define Bb 4
#define Ss 512
#define Dd 512
#define Hh 1024
#define Tt 64
#define Ee 8
#define NSTEPS 4
#define Nn (Bb*Ss)   // 2048 tokens

// ---------------- scratch (static device memory; no allocation) ----------------
__device__ float g_xt[(size_t)Ee*Nn*Dd];    // 32 MB  running state x_t (E,N,D)
__device__ float g_h1[(size_t)Ee*Nn*Hh];    // 64 MB  hidden 1 (E,N,H)
__device__ float g_h2[(size_t)Ee*Nn*Hh];    // 64 MB  hidden 2 (E,N,H)
__device__ float g_comb[Nn*Ee];             // dense combine weights
__device__ float g_probs[Nn*Ee];            // softmax probs (for lb loss)
__device__ float g_lse2[Nn];                // logsumexp^2 per token
__device__ float g_beff[Ee*Hh];             // per-step effective bias for GEMM1

// ---------------- router: logits, softmax, top-2, aux scratch ----------------
__global__ void router_kernel(const float* __restrict__ x, const float* __restrict__ gw) {
    int n = blockIdx.x;
    __shared__ float xs[Dd];
    __shared__ float lg[Ee];
    int tid = threadIdx.x;
    for (int c = tid; c < Dd; c += 256) xs[c] = x[(size_t)n*Dd + c];
    __syncthreads();
    int w = tid >> 5, lane = tid & 31;
    // 8 warps, one expert each
    float s = 0.f;
    const float* wrow = gw + (size_t)w*Dd;
    for (int c = lane; c < Dd; c += 32) s += xs[c]*wrow[c];
    #pragma unroll
    for (int o = 16; o; o >>= 1) s += __shfl_xor_sync(0xffffffffu, s, o);
    if (lane == 0) lg[w] = s;
    __syncthreads();
    if (tid == 0) {
        float m = lg[0];
        #pragma unroll
        for (int e = 1; e < Ee; e++) m = fmaxf(m, lg[e]);
        float ex[Ee], sum = 0.f;
        #pragma unroll
        for (int e = 0; e < Ee; e++) { ex[e] = expf(lg[e]-m); sum += ex[e]; }
        float lse = m + logf(sum);
        g_lse2[n] = lse*lse;
        float p[Ee];
        #pragma unroll
        for (int e = 0; e < Ee; e++) { p[e] = ex[e]/sum; g_probs[n*Ee+e] = p[e]; }
        int i1 = 0;
        #pragma unroll
        for (int e = 1; e < Ee; e++) if (p[e] > p[i1]) i1 = e;
        int i2 = (i1 == 0) ? 1 : 0;
        #pragma unroll
        for (int e = 0; e < Ee; e++) { if (e == i1) continue; if (p[e] > p[i2]) i2 = e; }
        float denom = p[i1] + p[i2] + 1e-9f;
        #pragma unroll
        for (int e = 0; e < Ee; e++) g_comb[n*Ee+e] = 0.f;
        g_comb[n*Ee+i1] = p[i1]/denom;
        g_comb[n*Ee+i2] = p[i2]/denom;
    }
}

// broadcast x -> x_t for all experts
__global__ void bcast_kernel(const float* __restrict__ x) {
    size_t idx = (size_t)blockIdx.x*256 + threadIdx.x;
    if (idx < (size_t)Ee*Nn*Dd) g_xt[idx] = x[idx % ((size_t)Nn*Dd)];
}

// per-step effective bias: b1 + t_emb @ W1[:, :, D:]  (t_emb = [sin(t f), cos(t f)])
__global__ void beff_kernel(const float* __restrict__ W1, const float* __restrict__ b1, float t) {
    int idx = blockIdx.x*256 + threadIdx.x;
    if (idx >= Ee*Hh) return;
    const float* wrow = W1 + (size_t)idx*(Dd+Tt) + Dd;
    float s = b1[idx];
    const float c0 = -9.210340371976184f / 31.0f;  // -ln(10000)/(half-1)
    #pragma unroll
    for (int i = 0; i < 32; i++) {
        float f = expf(c0 * (float)i);
        float a = t * f;
        s += sinf(a)*wrow[i] + cosf(a)*wrow[32+i];
    }
    g_beff[idx] = s;
}

// ---------------- batched NT GEMM: C[e] = A[e](MxK) * W[e](HoxK)^T ----------------
// BM=128, BN=64, BK=16, 256 threads, 8x4 register tile per thread.
template<bool SILU, bool AXPY>
__global__ void gemm_nt(const float* __restrict__ A, const float* __restrict__ W,
                        const float* __restrict__ bias, float* __restrict__ C,
                        int M, int Kd, int Ho, int ldW, float scale) {
    const int BM = 128, BN = 64, BK = 16;
    __shared__ float As[BK][BM];
    __shared__ float Bs[BK][BN];
    int e = blockIdx.z;
    A    += (size_t)e*M*Kd;
    W    += (size_t)e*Ho*ldW;
    bias += (size_t)e*Ho;
    C    += (size_t)e*M*Ho;
    int m0 = blockIdx.y*BM, n0 = blockIdx.x*BN;
    int tid = threadIdx.x;
    int tx = tid & 15, ty = tid >> 4;
    float acc[8][4];
    #pragma unroll
    for (int i = 0; i < 8; i++)
        #pragma unroll
        for (int j = 0; j < 4; j++) acc[i][j] = 0.f;

    int arow = tid >> 2;           // 0..63
    int acol = (tid & 3) * 4;      // 0,4,8,12

    for (int k0 = 0; k0 < Kd; k0 += BK) {
        // A tile 128x16 (two row passes), transposed into k-major SMEM
        #pragma unroll
        for (int p = 0; p < 2; p++) {
            int r = arow + p*64;
            float4 v = *(const float4*)(A + (size_t)(m0+r)*Kd + k0 + acol);
            As[acol+0][r] = v.x; As[acol+1][r] = v.y; As[acol+2][r] = v.z; As[acol+3][r] = v.w;
        }
        // W tile 64x16
        {
            float4 v = *(const float4*)(W + (size_t)(n0+arow)*ldW + k0 + acol);
            Bs[acol+0][arow] = v.x; Bs[acol+1][arow] = v.y; Bs[acol+2][arow] = v.z; Bs[acol+3][arow] = v.w;
        }
        __syncthreads();
        #pragma unroll
        for (int k = 0; k < BK; k++) {
            float4 a0 = *(const float4*)&As[k][ty*8];
            float4 a1 = *(const float4*)&As[k][ty*8+4];
            float4 wv4 = *(const float4*)&Bs[k][tx*4];
            float av[8] = {a0.x,a0.y,a0.z,a0.w,a1.x,a1.y,a1.z,a1.w};
            float wv[4] = {wv4.x,wv4.y,wv4.z,wv4.w};
            #pragma unroll
            for (int i = 0; i < 8; i++)
                #pragma unroll
                for (int j = 0; j < 4; j++)
                    acc[i][j] += av[i]*wv[j];
        }
        __syncthreads();
    }

    #pragma unroll
    for (int i = 0; i < 8; i++) {
        int m = m0 + ty*8 + i;
        #pragma unroll
        for (int j = 0; j < 4; j++) {
            int h = n0 + tx*4 + j;
            float v = acc[i][j] + bias[h];
            if (SILU) v = v / (1.f + expf(-v));
            if (AXPY) C[(size_t)m*Ho + h] += scale * v;
            else      C[(size_t)m*Ho + h] = v;
        }
    }
}

// ---------------- row LayerNorm over H=1024, in place ----------------
__global__ void ln_kernel(float* __restrict__ h, const float* __restrict__ g,
                          const float* __restrict__ be) {
    const int L = Hh;
    int row = blockIdx.x;           // e*N + n
    int e = row / Nn;
    float* hp = h + (size_t)row*L;
    const float* gp = g + (size_t)e*L;
    const float* bp = be + (size_t)e*L;
    __shared__ float buf[Hh];
    __shared__ float red[256];
    int tid = threadIdx.x;
    float s = 0.f;
    for (int j = tid; j < L; j += 256) { float v = hp[j]; buf[j] = v; s += v; }
    red[tid] = s; __syncthreads();
    #pragma unroll
    for (int o = 128; o; o >>= 1) { if (tid < o) red[tid] += red[tid+o]; __syncthreads(); }
    float mu = red[0] / L;
    __syncthreads();
    float s2 = 0.f;
    for (int j = tid; j < L; j += 256) { float d = buf[j]-mu; s2 += d*d; }
    red[tid] = s2; __syncthreads();
    #pragma unroll
    for (int o = 128; o; o >>= 1) { if (tid < o) red[tid] += red[tid+o]; __syncthreads(); }
    float rstd = rsqrtf(red[0]/L + 1e-5f);
    for (int j = tid; j < L; j += 256) hp[j] = (buf[j]-mu)*rstd*gp[j] + bp[j];
}

// ---------------- combine: out[n,d] = sum_e comb[n,e] * x_t[e,n,d] ----------------
__global__ void combine_kernel(float* __restrict__ out) {
    size_t idx = (size_t)blockIdx.x*256 + threadIdx.x;
    if (idx >= (size_t)Nn*Dd) return;
    int n = (int)(idx / Dd);
    float s = 0.f;
    #pragma unroll
    for (int e = 0; e < Ee; e++) s += g_comb[n*Ee+e] * g_xt[(size_t)e*Nn*Dd + idx];
    out[idx] = s;
}

// ---------------- aux losses -> tail of d_out ----------------
__global__ void aux_kernel(float* __restrict__ out, int out_size) {
    __shared__ float red[256];
    __shared__ float pe[Ee];
    int tid = threadIdx.x;
    float s = 0.f;
    for (int n = tid; n < Nn; n += 256) s += g_lse2[n];
    red[tid] = s; __syncthreads();
    #pragma unroll
    for (int o = 128; o; o >>= 1) { if (tid < o) red[tid] += red[tid+o]; __syncthreads(); }
    float z = red[0] / Nn;
    for (int e = 0; e < Ee; e++) {
        __syncthreads();
        float t = 0.f;
        for (int n = tid; n < Nn; n += 256) t += g_probs[n*Ee+e];
        red[tid] = t; __syncthreads();
        #pragma unroll
        for (int o = 128; o; o >>= 1) { if (tid < o) red[tid] += red[tid+o]; __syncthreads(); }
        if (tid == 0) pe[e] = red[0] / Nn;
    }
    __syncthreads();
    if (tid == 0) {
        float lb = 0.f;
        #pragma unroll
        for (int e = 0; e < Ee; e++) { float d = pe[e] - 1.0f/Ee; lb += d*d; }
        lb *= (float)Ee;
        float aux = 0.001f*z + 0.01f*lb;
        for (long long i = (long long)Nn*Dd; i < out_size; i++) out[i] = aux;
    }
}

extern "C" void kernel_launch(void* const* d_in, const int* in_sizes, int n_in,
                              void* d_out, int out_size) {
    const float* x   = (const float*)d_in[0];
    const float* gw  = (const float*)d_in[1];
    const float* W1  = (const float*)d_in[2];
    const float* b1  = (const float*)d_in[3];
    const float* g1  = (const float*)d_in[4];
    const float* be1 = (const float*)d_in[5];
    const float* W2  = (const float*)d_in[6];
    const float* b2  = (const float*)d_in[7];
    const float* g2  = (const float*)d_in[8];
    const float* be2 = (const float*)d_in[9];
    const float* W3  = (const float*)d_in[10];
    const float* b3  = (const float*)d_in[11];
    float* out = (float*)d_out;

    float *xt, *h1, *h2, *beff;
    cudaGetSymbolAddress((void**)&xt,   g_xt);
    cudaGetSymbolAddress((void**)&h1,   g_h1);
    cudaGetSymbolAddress((void**)&h2,   g_h2);
    cudaGetSymbolAddress((void**)&beff, g_beff);

    router_kernel<<<Nn, 256>>>(x, gw);
    bcast_kernel<<<(int)(((size_t)Ee*Nn*Dd + 255)/256), 256>>>(x);

    const float dt = 1.0f / NSTEPS;
    for (int s = 0; s < NSTEPS; s++) {
        float t = s * dt;
        beff_kernel<<<(Ee*Hh + 255)/256, 256>>>(W1, b1, t);
        // h1 = SiLU(x_t @ W1[:, :, :512]^T + beff)   (t_emb folded into beff)
        gemm_nt<true,  false><<<dim3(Hh/64, Nn/128, Ee), 256>>>(xt, W1, beff, h1, Nn, Dd, Hh, Dd+Tt, 1.f);
        ln_kernel<<<Ee*Nn, 256>>>(h1, g1, be1);
        // h2 = SiLU(h1 @ W2^T + b2)
        gemm_nt<true,  false><<<dim3(Hh/64, Nn/128, Ee), 256>>>(h1, W2, b2, h2, Nn, Hh, Hh, Hh, 1.f);
        ln_kernel<<<Ee*Nn, 256>>>(h2, g2, be2);
        // x_t += dt * (h2 @ W3^T + b3)
        gemm_nt<false, true ><<<dim3(Dd/64, Nn/128, Ee), 256>>>(h2, W3, b3, xt, Nn, Hh, Dd, Hh, dt);
    }

    combine_kernel<<<(int)(((size_t)Nn*Dd + 255)/256), 256>>>(out);
    aux_kernel<<<1, 256>>>(out, out_size);
}

// round 3
// speedup vs baseline: 2.2195x; 2.2195x over previous
#include <cuda_runtime.h>
#include <cuda_bf16.h>
#include <math.h>
#include <stdint.h>

#define Bb 4
#define Ss 512
#define Dd 512
#define Hh 1024
#define Tt 64
#define Ee 8
#define NSTEPS 4
#define Nn (Bb*Ss)   // 2048 tokens

// ---------------- scratch (static device memory; no allocation) ----------------
__device__ float g_xt[(size_t)Ee*Nn*Dd];
__device__ float g_h1[(size_t)Ee*Nn*Hh];
__device__ float g_h2[(size_t)Ee*Nn*Hh];
__device__ float g_comb[Nn*Ee];
__device__ float g_probs[Nn*Ee];
__device__ float g_lse2[Nn];
__device__ float g_beff[Ee*Hh];
__device__ __nv_bfloat16 g_w1hi[(size_t)Ee*Hh*Dd];
__device__ __nv_bfloat16 g_w1lo[(size_t)Ee*Hh*Dd];
__device__ __nv_bfloat16 g_w2hi[(size_t)Ee*Hh*Hh];
__device__ __nv_bfloat16 g_w2lo[(size_t)Ee*Hh*Hh];
__device__ __nv_bfloat16 g_w3hi[(size_t)Ee*Dd*Hh];
__device__ __nv_bfloat16 g_w3lo[(size_t)Ee*Dd*Hh];

__device__ __forceinline__ uint32_t smem_u32(const void* p) {
    uint32_t a;
    asm("{ .reg .u64 t; cvta.to.shared.u64 t, %1; cvt.u32.u64 %0, t; }" : "=r"(a) : "l"(p));
    return a;
}
__device__ __forceinline__ void ldmx4(uint32_t* r, uint32_t addr) {
    asm volatile("ldmatrix.sync.aligned.m8n8.x4.shared.b16 {%0,%1,%2,%3}, [%4];"
        : "=r"(r[0]), "=r"(r[1]), "=r"(r[2]), "=r"(r[3]) : "r"(addr));
}
__device__ __forceinline__ void mma_bf16(float* d, const uint32_t* a, uint32_t b0, uint32_t b1) {
    asm volatile("mma.sync.aligned.m16n8k16.row.col.f32.bf16.bf16.f32 "
        "{%0,%1,%2,%3}, {%4,%5,%6,%7}, {%8,%9}, {%0,%1,%2,%3};"
        : "+f"(d[0]), "+f"(d[1]), "+f"(d[2]), "+f"(d[3])
        : "r"(a[0]), "r"(a[1]), "r"(a[2]), "r"(a[3]), "r"(b0), "r"(b1));
}

// ---------------- router ----------------
__global__ void router_kernel(const float* __restrict__ x, const float* __restrict__ gw) {
    int n = blockIdx.x;
    __shared__ float xs[Dd];
    __shared__ float lg[Ee];
    int tid = threadIdx.x;
    for (int c = tid; c < Dd; c += 256) xs[c] = x[(size_t)n*Dd + c];
    __syncthreads();
    int w = tid >> 5, lane = tid & 31;
    float s = 0.f;
    const float* wrow = gw + (size_t)w*Dd;
    for (int c = lane; c < Dd; c += 32) s += xs[c]*wrow[c];
    #pragma unroll
    for (int o = 16; o; o >>= 1) s += __shfl_xor_sync(0xffffffffu, s, o);
    if (lane == 0) lg[w] = s;
    __syncthreads();
    if (tid == 0) {
        float m = lg[0];
        #pragma unroll
        for (int e = 1; e < Ee; e++) m = fmaxf(m, lg[e]);
        float ex[Ee], sum = 0.f;
        #pragma unroll
        for (int e = 0; e < Ee; e++) { ex[e] = expf(lg[e]-m); sum += ex[e]; }
        float lse = m + logf(sum);
        g_lse2[n] = lse*lse;
        float p[Ee];
        #pragma unroll
        for (int e = 0; e < Ee; e++) { p[e] = ex[e]/sum; g_probs[n*Ee+e] = p[e]; }
        int i1 = 0;
        #pragma unroll
        for (int e = 1; e < Ee; e++) if (p[e] > p[i1]) i1 = e;
        int i2 = (i1 == 0) ? 1 : 0;
        #pragma unroll
        for (int e = 0; e < Ee; e++) { if (e == i1) continue; if (p[e] > p[i2]) i2 = e; }
        float denom = p[i1] + p[i2] + 1e-9f;
        #pragma unroll
        for (int e = 0; e < Ee; e++) g_comb[n*Ee+e] = 0.f;
        g_comb[n*Ee+i1] = p[i1]/denom;
        g_comb[n*Ee+i2] = p[i2]/denom;
    }
}

__global__ void bcast_kernel(const float* __restrict__ x) {
    size_t idx = (size_t)blockIdx.x*256 + threadIdx.x;
    if (idx < (size_t)Ee*Nn*Dd) g_xt[idx] = x[idx % ((size_t)Nn*Dd)];
}

__global__ void beff_kernel(const float* __restrict__ W1, const float* __restrict__ b1, float t) {
    int idx = blockIdx.x*256 + threadIdx.x;
    if (idx >= Ee*Hh) return;
    const float* wrow = W1 + (size_t)idx*(Dd+Tt) + Dd;
    float s = b1[idx];
    const float c0 = -9.210340371976184f / 31.0f;
    #pragma unroll
    for (int i = 0; i < 32; i++) {
        float f = expf(c0 * (float)i);
        float a = t * f;
        s += sinf(a)*wrow[i] + cosf(a)*wrow[32+i];
    }
    g_beff[idx] = s;
}

// ---------------- weight split: fp32 -> bf16 hi + bf16 lo ----------------
__global__ void wsplit_kernel(const float* __restrict__ src, int ld, int cols,
                              __nv_bfloat16* __restrict__ hi, __nv_bfloat16* __restrict__ lo,
                              long long total) {
    long long idx = (long long)blockIdx.x*256 + threadIdx.x;
    if (idx >= total) return;
    long long r = idx / cols, c = idx % cols;
    float v = src[r*ld + c];
    __nv_bfloat16 h = __float2bfloat16_rn(v);
    float hf = __bfloat162float(h);
    hi[idx] = h;
    lo[idx] = __float2bfloat16_rn(v - hf);
}

// ================= HMMA batched NT GEMM =================
// C[e](2048 x Ho) = A[e](2048 x K) * W[e](Ho x K)^T, bf16 hi/lo 3-MMA split.
// BM=128, BN=128, BK=64, 256 threads (8 warps, 2M x 4N of 64x32 warp tiles).
// SMEM: pitch 72 bf16 (144B) rows; stage = {Ah,Al,Wh,Wl} each 128x72.
#define PITCHB 144
#define ASZ    (128*PITCHB)      // 18432
#define STAGE  (4*ASZ)           // 73728
#define SMEM_DYN (2*STAGE)       // 147456

template<int EPI>
__global__ __launch_bounds__(256, 1)
void gemm_hmma(const float* __restrict__ A,
               const __nv_bfloat16* __restrict__ Whi, const __nv_bfloat16* __restrict__ Wlo,
               const float* __restrict__ bias, float* __restrict__ C,
               int K, int Ho, float scale) {
    extern __shared__ __align__(128) char smem[];
    const uint32_t sbase = smem_u32(smem);
    int tid = threadIdx.x, wid = tid >> 5, lane = tid & 31;
    int wm = wid & 1, wn = wid >> 1;
    int e = blockIdx.z;
    A    += (size_t)e*Nn*K;
    Whi  += (size_t)e*Ho*K;
    Wlo  += (size_t)e*Ho*K;
    bias += (size_t)e*Ho;
    C    += (size_t)e*Nn*Ho;
    const int m0 = blockIdx.y*128, n0 = blockIdx.x*128;

    // per-lane ldmatrix addressing
    int part = lane >> 3, rip = lane & 7;
    int lrow  = (part & 1)*8 + rip;
    int lcolB = (part >> 1)*16;   // bytes

    float acc[4][4][4];
    #pragma unroll
    for (int i = 0; i < 4; i++)
        #pragma unroll
        for (int j = 0; j < 4; j++)
            #pragma unroll
            for (int q = 0; q < 4; q++) acc[i][j][q] = 0.f;

    const int nc = K >> 6;

    float4 areg[8];
    uint4  whreg[4], wlreg[4];

    // ---- load chunk 0 into regs ----
    {
        const float* Ab = A + (size_t)m0*K;
        #pragma unroll
        for (int i = 0; i < 8; i++) {
            int flat = tid + 256*i, r = flat >> 4, c4 = flat & 15;
            areg[i] = *(const float4*)(Ab + (size_t)r*K + c4*4);
        }
        const __nv_bfloat16* Wbh = Whi + (size_t)n0*K;
        const __nv_bfloat16* Wbl = Wlo + (size_t)n0*K;
        #pragma unroll
        for (int i = 0; i < 4; i++) {
            int flat = tid + 256*i, r = flat >> 3, u = flat & 7;
            whreg[i] = *(const uint4*)(Wbh + (size_t)r*K + u*8);
            wlreg[i] = *(const uint4*)(Wbl + (size_t)r*K + u*8);
        }
    }

    for (int ck = 0; ck < nc; ck++) {
        int b = ck & 1;
        char* st = smem + b*STAGE;
        // ---- store regs -> smem (convert A) ----
        #pragma unroll
        for (int i = 0; i < 8; i++) {
            int flat = tid + 256*i, r = flat >> 4, c4 = flat & 15;
            float4 v = areg[i];
            __nv_bfloat162 h0 = __float22bfloat162_rn(make_float2(v.x, v.y));
            __nv_bfloat162 h1 = __float22bfloat162_rn(make_float2(v.z, v.w));
            float2 f0 = __bfloat1622float2(h0), f1 = __bfloat1622float2(h1);
            __nv_bfloat162 l0 = __float22bfloat162_rn(make_float2(v.x - f0.x, v.y - f0.y));
            __nv_bfloat162 l1 = __float22bfloat162_rn(make_float2(v.z - f1.x, v.w - f1.y));
            uint32_t off = r*PITCHB + c4*8;
            *(uint2*)(st + off)       = make_uint2(*(uint32_t*)&h0, *(uint32_t*)&h1);
            *(uint2*)(st + ASZ + off) = make_uint2(*(uint32_t*)&l0, *(uint32_t*)&l1);
        }
        #pragma unroll
        for (int i = 0; i < 4; i++) {
            int flat = tid + 256*i, r = flat >> 3, u = flat & 7;
            uint32_t off = r*PITCHB + u*16;
            *(uint4*)(st + 2*ASZ + off) = whreg[i];
            *(uint4*)(st + 3*ASZ + off) = wlreg[i];
        }
        __syncthreads();

        // ---- prefetch next chunk ----
        if (ck + 1 < nc) {
            const float* Ab = A + (size_t)m0*K + (ck+1)*64;
            #pragma unroll
            for (int i = 0; i < 8; i++) {
                int flat = tid + 256*i, r = flat >> 4, c4 = flat & 15;
                areg[i] = *(const float4*)(Ab + (size_t)r*K + c4*4);
            }
            const __nv_bfloat16* Wbh = Whi + (size_t)n0*K + (ck+1)*64;
            const __nv_bfloat16* Wbl = Wlo + (size_t)n0*K + (ck+1)*64;
            #pragma unroll
            for (int i = 0; i < 4; i++) {
                int flat = tid + 256*i, r = flat >> 3, u = flat & 7;
                whreg[i] = *(const uint4*)(Wbh + (size_t)r*K + u*8);
                wlreg[i] = *(const uint4*)(Wbl + (size_t)r*K + u*8);
            }
        }

        // ---- compute on stage b ----
        uint32_t stb = sbase + b*STAGE;
        #pragma unroll
        for (int ks = 0; ks < 4; ks++) {
            int kb = ks*32;  // bytes within row
            uint32_t ah[4][4], al[4][4];
            #pragma unroll
            for (int mi = 0; mi < 4; mi++) {
                uint32_t ad = stb + (wm*64 + mi*16 + lrow)*PITCHB + kb + lcolB;
                ldmx4(ah[mi], ad);
                ldmx4(al[mi], ad + ASZ);
            }
            uint32_t wh[4][2], wl[4][2];
            #pragma unroll
            for (int p = 0; p < 2; p++) {
                uint32_t wd = stb + 2*ASZ + (wn*32 + p*16 + lrow)*PITCHB + kb + lcolB;
                uint32_t r4[4];
                ldmx4(r4, wd);
                wh[2*p][0] = r4[0]; wh[2*p][1] = r4[2];
                wh[2*p+1][0] = r4[1]; wh[2*p+1][1] = r4[3];
                ldmx4(r4, wd + ASZ);
                wl[2*p][0] = r4[0]; wl[2*p][1] = r4[2];
                wl[2*p+1][0] = r4[1]; wl[2*p+1][1] = r4[3];
            }
            #pragma unroll
            for (int mi = 0; mi < 4; mi++)
                #pragma unroll
                for (int nt = 0; nt < 4; nt++) {
                    mma_bf16(acc[mi][nt], ah[mi], wh[nt][0], wh[nt][1]);
                    mma_bf16(acc[mi][nt], ah[mi], wl[nt][0], wl[nt][1]);
                    mma_bf16(acc[mi][nt], al[mi], wh[nt][0], wh[nt][1]);
                }
        }
        __syncthreads();
    }

    // ---- epilogue straight from registers ----
    int r_l = lane >> 2, c_l = (lane & 3)*2;
    #pragma unroll
    for (int nt = 0; nt < 4; nt++) {
        int col = n0 + wn*32 + nt*8 + c_l;
        float2 bv = *(const float2*)(bias + col);
        #pragma unroll
        for (int mi = 0; mi < 4; mi++) {
            int row0 = m0 + wm*64 + mi*16 + r_l;
            float v0 = acc[mi][nt][0] + bv.x;
            float v1 = acc[mi][nt][1] + bv.y;
            float v2 = acc[mi][nt][2] + bv.x;
            float v3 = acc[mi][nt][3] + bv.y;
            if (EPI == 0) {
                v0 = v0 / (1.f + __expf(-v0));
                v1 = v1 / (1.f + __expf(-v1));
                v2 = v2 / (1.f + __expf(-v2));
                v3 = v3 / (1.f + __expf(-v3));
                *(float2*)(C + (size_t)row0*Ho + col)     = make_float2(v0, v1);
                *(float2*)(C + (size_t)(row0+8)*Ho + col) = make_float2(v2, v3);
            } else {
                float* p0 = C + (size_t)row0*Ho + col;
                float* p1 = C + (size_t)(row0+8)*Ho + col;
                float2 o0 = *(float2*)p0, o1 = *(float2*)p1;
                *(float2*)p0 = make_float2(o0.x + scale*v0, o0.y + scale*v1);
                *(float2*)p1 = make_float2(o1.x + scale*v2, o1.y + scale*v3);
            }
        }
    }
}

// ---------------- row LayerNorm over H=1024, in place ----------------
__global__ void ln_kernel(float* __restrict__ h, const float* __restrict__ g,
                          const float* __restrict__ be) {
    const int L = Hh;
    int row = blockIdx.x;
    int e = row / Nn;
    float* hp = h + (size_t)row*L;
    const float* gp = g + (size_t)e*L;
    const float* bp = be + (size_t)e*L;
    __shared__ float buf[Hh];
    __shared__ float red[256];
    int tid = threadIdx.x;
    float s = 0.f;
    for (int j = tid; j < L; j += 256) { float v = hp[j]; buf[j] = v; s += v; }
    red[tid] = s; __syncthreads();
    #pragma unroll
    for (int o = 128; o; o >>= 1) { if (tid < o) red[tid] += red[tid+o]; __syncthreads(); }
    float mu = red[0] / L;
    __syncthreads();
    float s2 = 0.f;
    for (int j = tid; j < L; j += 256) { float d = buf[j]-mu; s2 += d*d; }
    red[tid] = s2; __syncthreads();
    #pragma unroll
    for (int o = 128; o; o >>= 1) { if (tid < o) red[tid] += red[tid+o]; __syncthreads(); }
    float rstd = rsqrtf(red[0]/L + 1e-5f);
    for (int j = tid; j < L; j += 256) hp[j] = (buf[j]-mu)*rstd*gp[j] + bp[j];
}

// ---------------- combine ----------------
__global__ void combine_kernel(float* __restrict__ out) {
    size_t idx = (size_t)blockIdx.x*256 + threadIdx.x;
    if (idx >= (size_t)Nn*Dd) return;
    int n = (int)(idx / Dd);
    float s = 0.f;
    #pragma unroll
    for (int e = 0; e < Ee; e++) s += g_comb[n*Ee+e] * g_xt[(size_t)e*Nn*Dd + idx];
    out[idx] = s;
}

// ---------------- aux losses ----------------
__global__ void aux_kernel(float* __restrict__ out, int out_size) {
    __shared__ float red[256];
    __shared__ float pe[Ee];
    int tid = threadIdx.x;
    float s = 0.f;
    for (int n = tid; n < Nn; n += 256) s += g_lse2[n];
    red[tid] = s; __syncthreads();
    #pragma unroll
    for (int o = 128; o; o >>= 1) { if (tid < o) red[tid] += red[tid+o]; __syncthreads(); }
    float z = red[0] / Nn;
    for (int e = 0; e < Ee; e++) {
        __syncthreads();
        float t = 0.f;
        for (int n = tid; n < Nn; n += 256) t += g_probs[n*Ee+e];
        red[tid] = t; __syncthreads();
        #pragma unroll
        for (int o = 128; o; o >>= 1) { if (tid < o) red[tid] += red[tid+o]; __syncthreads(); }
        if (tid == 0) pe[e] = red[0] / Nn;
    }
    __syncthreads();
    if (tid == 0) {
        float lb = 0.f;
        #pragma unroll
        for (int e = 0; e < Ee; e++) { float d = pe[e] - 1.0f/Ee; lb += d*d; }
        lb *= (float)Ee;
        float aux = 0.001f*z + 0.01f*lb;
        for (long long i = (long long)Nn*Dd; i < out_size; i++) out[i] = aux;
    }
}

extern "C" void kernel_launch(void* const* d_in, const int* in_sizes, int n_in,
                              void* d_out, int out_size) {
    const float* x   = (const float*)d_in[0];
    const float* gw  = (const float*)d_in[1];
    const float* W1  = (const float*)d_in[2];
    const float* b1  = (const float*)d_in[3];
    const float* g1  = (const float*)d_in[4];
    const float* be1 = (const float*)d_in[5];
    const float* W2  = (const float*)d_in[6];
    const float* b2  = (const float*)d_in[7];
    const float* g2  = (const float*)d_in[8];
    const float* be2 = (const float*)d_in[9];
    const float* W3  = (const float*)d_in[10];
    const float* b3  = (const float*)d_in[11];
    float* out = (float*)d_out;

    float *xt, *h1, *h2, *beff;
    __nv_bfloat16 *w1h, *w1l, *w2h, *w2l, *w3h, *w3l;
    cudaGetSymbolAddress((void**)&xt,   g_xt);
    cudaGetSymbolAddress((void**)&h1,   g_h1);
    cudaGetSymbolAddress((void**)&h2,   g_h2);
    cudaGetSymbolAddress((void**)&beff, g_beff);
    cudaGetSymbolAddress((void**)&w1h,  g_w1hi);
    cudaGetSymbolAddress((void**)&w1l,  g_w1lo);
    cudaGetSymbolAddress((void**)&w2h,  g_w2hi);
    cudaGetSymbolAddress((void**)&w2l,  g_w2lo);
    cudaGetSymbolAddress((void**)&w3h,  g_w3hi);
    cudaGetSymbolAddress((void**)&w3l,  g_w3lo);

    cudaFuncSetAttribute(gemm_hmma<0>, cudaFuncAttributeMaxDynamicSharedMemorySize, SMEM_DYN);
    cudaFuncSetAttribute(gemm_hmma<1>, cudaFuncAttributeMaxDynamicSharedMemorySize, SMEM_DYN);

    router_kernel<<<Nn, 256>>>(x, gw);
    bcast_kernel<<<(int)(((size_t)Ee*Nn*Dd + 255)/256), 256>>>(x);

    {
        long long t1 = (long long)Ee*Hh*Dd;
        long long t2 = (long long)Ee*Hh*Hh;
        long long t3 = (long long)Ee*Dd*Hh;
        wsplit_kernel<<<(int)((t1+255)/256), 256>>>(W1, Dd+Tt, Dd, w1h, w1l, t1);
        wsplit_kernel<<<(int)((t2+255)/256), 256>>>(W2, Hh,    Hh, w2h, w2l, t2);
        wsplit_kernel<<<(int)((t3+255)/256), 256>>>(W3, Hh,    Hh, w3h, w3l, t3);
    }

    const float dt = 1.0f / NSTEPS;
    for (int s = 0; s < NSTEPS; s++) {
        float t = s * dt;
        beff_kernel<<<(Ee*Hh + 255)/256, 256>>>(W1, b1, t);
        gemm_hmma<0><<<dim3(Hh/128, Nn/128, Ee), 256, SMEM_DYN>>>(xt, w1h, w1l, beff, h1, Dd, Hh, 1.f);
        ln_kernel<<<Ee*Nn, 256>>>(h1, g1, be1);
        gemm_hmma<0><<<dim3(Hh/128, Nn/128, Ee), 256, SMEM_DYN>>>(h1, w2h, w2l, b2, h2, Hh, Hh, 1.f);
        ln_kernel<<<Ee*Nn, 256>>>(h2, g2, be2);
        gemm_hmma<1><<<dim3(Dd/128, Nn/128, Ee), 256, SMEM_DYN>>>(h2, w3h, w3l, b3, xt, Hh, Dd, dt);
    }

    combine_kernel<<<(int)(((size_t)Nn*Dd + 255)/256), 256>>>(out);
    aux_kernel<<<1, 256>>>(out, out_size);
}